// round 1
// baseline (speedup 1.0000x reference)
#include <cuda_runtime.h>

// SecGELU: out = (y>=0 ? x : 0) - table[min(|y|, 4095)]
// where X = rint(x * 2^16), y = floor(X / 64).
//
// Pure HBM-streaming elementwise op. 256 MiB in + 256 MiB out.
// Table (16 KB) staged in shared memory; float4 vectorized I/O.

#define SECGELU_TABLE_SIZE 4096
#define THREADS 256

__device__ __forceinline__ float secgelu_one(float xi, const float* __restrict__ s_tab) {
    // X = round(x * 65536)  (round-half-even, matches jnp.round)
    float X = rintf(xi * 65536.0f);
    // y = floor(X / 64) — exact: X is integer-valued, /64 is a power-of-two scale
    float yf = floorf(X * 0.015625f);
    float a = fabsf(yf);
    int c = (a < (float)SECGELU_TABLE_SIZE) ? (int)a : (SECGELU_TABLE_SIZE - 1);
    float t = s_tab[c];
    return (yf >= 0.0f ? xi : 0.0f) - t;
}

__global__ void __launch_bounds__(THREADS)
secgelu_vec4_kernel(const float* __restrict__ x,
                    const float* __restrict__ table,
                    float* __restrict__ out,
                    long long n4) {
    __shared__ float s_tab[SECGELU_TABLE_SIZE];
    #pragma unroll
    for (int i = 0; i < SECGELU_TABLE_SIZE / THREADS; i++)
        s_tab[threadIdx.x + i * THREADS] = table[threadIdx.x + i * THREADS];
    __syncthreads();

    long long idx = (long long)blockIdx.x * THREADS + threadIdx.x;
    long long stride = (long long)gridDim.x * THREADS;
    for (; idx < n4; idx += stride) {
        float4 v = reinterpret_cast<const float4*>(x)[idx];
        float4 r;
        r.x = secgelu_one(v.x, s_tab);
        r.y = secgelu_one(v.y, s_tab);
        r.z = secgelu_one(v.z, s_tab);
        r.w = secgelu_one(v.w, s_tab);
        reinterpret_cast<float4*>(out)[idx] = r;
    }
}

__global__ void __launch_bounds__(THREADS)
secgelu_tail_kernel(const float* __restrict__ x,
                    const float* __restrict__ table,
                    float* __restrict__ out,
                    long long start, long long n) {
    long long i = start + (long long)blockIdx.x * THREADS + threadIdx.x;
    if (i >= n) return;
    float xi = x[i];
    float X = rintf(xi * 65536.0f);
    float yf = floorf(X * 0.015625f);
    float a = fabsf(yf);
    int c = (a < (float)SECGELU_TABLE_SIZE) ? (int)a : (SECGELU_TABLE_SIZE - 1);
    out[i] = (yf >= 0.0f ? xi : 0.0f) - table[c];
}

extern "C" void kernel_launch(void* const* d_in, const int* in_sizes, int n_in,
                              void* d_out, int out_size) {
    const float* x     = (const float*)d_in[0];
    const float* table = (const float*)d_in[1];
    float* out         = (float*)d_out;

    long long n  = (long long)in_sizes[0];
    long long n4 = n >> 2;

    if (n4 > 0) {
        long long blocks = (n4 + THREADS - 1) / THREADS;
        if (blocks > 2147483647LL) blocks = 2147483647LL;
        secgelu_vec4_kernel<<<(int)blocks, THREADS>>>(x, table, out, n4);
    }
    long long tail_start = n4 << 2;
    long long n_tail = n - tail_start;
    if (n_tail > 0) {
        long long tblocks = (n_tail + THREADS - 1) / THREADS;
        secgelu_tail_kernel<<<(int)tblocks, THREADS>>>(x, table, out, tail_start, n);
    }
}

// round 2
// speedup vs baseline: 1.4194x; 1.4194x over previous
#include <cuda_runtime.h>

// SecGELU: out = (i>=0 ? x : 0) - table[min(|i>>6|, 4095)]
// where i = rint(x * 2^16) as int32 (exact ring semantics).
//
// Integer fixed-point path: F2I.RN + SHF + IABS + IMNMX replaces the
// float rint/floor/fabs/compare chain. Table in shared memory.
// 4x float4 per thread, exact grid, batched loads for MLP.

#define SECGELU_TABLE_SIZE 4096
#define THREADS 256
#define V4_PER_THREAD 4   // 16 elements per thread
#define V4_PER_BLOCK (THREADS * V4_PER_THREAD)  // 1024 float4 = 4096 elems

__device__ __forceinline__ float secgelu_one(float xi, const float* __restrict__ s_tab) {
    int i = __float2int_rn(xi * 65536.0f);   // X = round(x * 2^16), round-half-even
    int y = i >> 6;                          // floor division by 64 (exact for negatives)
    int a = (y >= 0) ? y : -y;               // |y|  (IABS)
    int c = min(a, SECGELU_TABLE_SIZE - 1);  // clamp (IMNMX)
    float t = s_tab[c];
    return ((i >= 0) ? xi : 0.0f) - t;       // d*x - table[c]
}

__global__ void __launch_bounds__(THREADS)
secgelu_main_kernel(const float4* __restrict__ x4,
                    const float* __restrict__ table,
                    float4* __restrict__ out4) {
    __shared__ float s_tab[SECGELU_TABLE_SIZE];
    #pragma unroll
    for (int i = 0; i < SECGELU_TABLE_SIZE / THREADS; i++)
        s_tab[threadIdx.x + i * THREADS] = table[threadIdx.x + i * THREADS];
    __syncthreads();

    int base = blockIdx.x * V4_PER_BLOCK + threadIdx.x;

    // Front-batch all loads (MLP)
    float4 v[V4_PER_THREAD];
    #pragma unroll
    for (int k = 0; k < V4_PER_THREAD; k++)
        v[k] = x4[base + k * THREADS];

    float4 r[V4_PER_THREAD];
    #pragma unroll
    for (int k = 0; k < V4_PER_THREAD; k++) {
        r[k].x = secgelu_one(v[k].x, s_tab);
        r[k].y = secgelu_one(v[k].y, s_tab);
        r[k].z = secgelu_one(v[k].z, s_tab);
        r[k].w = secgelu_one(v[k].w, s_tab);
    }

    #pragma unroll
    for (int k = 0; k < V4_PER_THREAD; k++)
        out4[base + k * THREADS] = r[k];
}

__global__ void __launch_bounds__(THREADS)
secgelu_tail_kernel(const float* __restrict__ x,
                    const float* __restrict__ table,
                    float* __restrict__ out,
                    long long start, long long n) {
    long long i = start + (long long)blockIdx.x * THREADS + threadIdx.x;
    if (i >= n) return;
    float xi = x[i];
    int ii = __float2int_rn(xi * 65536.0f);
    int y = ii >> 6;
    int a = (y >= 0) ? y : -y;
    int c = min(a, SECGELU_TABLE_SIZE - 1);
    out[i] = ((ii >= 0) ? xi : 0.0f) - table[c];
}

extern "C" void kernel_launch(void* const* d_in, const int* in_sizes, int n_in,
                              void* d_out, int out_size) {
    const float* x     = (const float*)d_in[0];
    const float* table = (const float*)d_in[1];
    float* out         = (float*)d_out;

    long long n = (long long)in_sizes[0];
    long long elems_per_block = (long long)V4_PER_BLOCK * 4;  // 4096
    long long nblocks = n / elems_per_block;

    if (nblocks > 0) {
        secgelu_main_kernel<<<(int)nblocks, THREADS>>>(
            (const float4*)x, table, (float4*)out);
    }
    long long done = nblocks * elems_per_block;
    long long n_tail = n - done;
    if (n_tail > 0) {
        long long tblocks = (n_tail + THREADS - 1) / THREADS;
        secgelu_tail_kernel<<<(int)tblocks, THREADS>>>(x, table, out, done, n);
    }
}